// round 6
// baseline (speedup 1.0000x reference)
#include <cuda_runtime.h>
#include <cuda_fp16.h>
#include <cstdint>
#include <math.h>

// Problem shape (fixed)
#define Bb  4
#define Kk  8192
#define Dd  1024
#define Mm  (Bb * Kk)          // 32768 GEMM rows
#define NCH 32                 // scan chunks along K
#define LCH (Kk / NCH)         // 256 steps per chunk
#define CHN (Bb * Dd)          // 4096 independent channels

// Scratch (allocation-free rule: __device__ globals)
__device__ __half g_lamh[(size_t)Mm * Dd];    // 64 MiB fp16 lam
__device__ __half g_Wh[(size_t)Dd * Dd];      // 2 MiB fp16 W
__device__ float  g_A[NCH * CHN];
__device__ float  g_S[NCH * CHN];
__device__ float  g_P[NCH * CHN];

// ---------------------------------------------------------------------------
// f32 -> f16 conversion (W only, 2 MiB)
// ---------------------------------------------------------------------------
__global__ __launch_bounds__(256) void f2h_kernel(const float4* __restrict__ src,
                                                  uint2* __restrict__ dst, int n4)
{
    int i = blockIdx.x * blockDim.x + threadIdx.x;
    const int stride = gridDim.x * blockDim.x;
    for (; i < n4; i += stride) {
        float4 v = src[i];
        __half2 h0 = __floats2half2_rn(v.x, v.y);
        __half2 h1 = __floats2half2_rn(v.z, v.w);
        uint2 o;
        o.x = *reinterpret_cast<unsigned*>(&h0);
        o.y = *reinterpret_cast<unsigned*>(&h1);
        dst[i] = o;
    }
}

// ---------------------------------------------------------------------------
// FP16 tensor-core GEMM + sigmoid epilogue:  g_lamh = sigmoid(X @ W^T + b)
// 256 threads, BM=128 x BN=256, BK=32, 2x4 warps of 64x64, m16n8k16 HMMA.
// A path: X fp32 LDG (distance-2 reg prefetch) -> cvt -> STS.
// B path: W fp16 via 4-stage cp.async. pitch-40-halves smem.
// ---------------------------------------------------------------------------
#define BM 128
#define BN 256
#define BK 32
#define PITH 40                          // smem row pitch in halves (80 B)
#define NSTG 4
#define A_STGH (BM * PITH)               // 5120 halves / stage
#define B_STGH (BN * PITH)               // 10240 halves / stage
#define SMEM_HALVES (NSTG * (A_STGH + B_STGH))   // 61440 halves = 122880 B
#define NKT (Dd / BK)                    // 32 k-stages

__device__ __forceinline__ void cp16s(uint32_t smem_dst, const void* gmem_src) {
    asm volatile("cp.async.cg.shared.global [%0], [%1], 16;\n"
                 :: "r"(smem_dst), "l"(gmem_src));
}
__device__ __forceinline__ void cp_commit() {
    asm volatile("cp.async.commit_group;\n");
}
template <int N>
__device__ __forceinline__ void cp_wait() {
    asm volatile("cp.async.wait_group %0;\n" :: "n"(N));
}
__device__ __forceinline__ void mma_f16(float* d, const unsigned* a, const unsigned* b) {
    asm volatile(
        "mma.sync.aligned.m16n8k16.row.col.f32.f16.f16.f32 "
        "{%0,%1,%2,%3}, {%4,%5,%6,%7}, {%8,%9}, {%0,%1,%2,%3};\n"
        : "+f"(d[0]), "+f"(d[1]), "+f"(d[2]), "+f"(d[3])
        : "r"(a[0]), "r"(a[1]), "r"(a[2]), "r"(a[3]), "r"(b[0]), "r"(b[1]));
}

extern __shared__ __half smemh[];

__global__ __launch_bounds__(256, 1) void gemm_sigmoid_f16(
    const float* __restrict__ X,
    const float* __restrict__ bias)
{
    __half* As = smemh;                  // [NSTG][BM][PITH]
    __half* Bs = smemh + NSTG * A_STGH;  // [NSTG][BN][PITH]

    const int tid  = threadIdx.x;
    const int lane = tid & 31;
    const int wid  = tid >> 5;           // 8 warps: 2 (m) x 4 (n)
    const int wm0  = (wid & 1) * 64;
    const int wn0  = (wid >> 1) * 64;
    const int g    = lane >> 2;          // 0..7
    const int q    = lane & 3;           // 0..3
    const int m0b  = blockIdx.y * BM;
    const int n0b  = blockIdx.x * BN;

    const uint32_t sB = (uint32_t)__cvta_generic_to_shared(Bs);

    float acc[4][8][4];
    #pragma unroll
    for (int mi = 0; mi < 4; mi++)
        #pragma unroll
        for (int ni = 0; ni < 8; ni++)
            #pragma unroll
            for (int r = 0; r < 4; r++)
                acc[mi][ni][r] = 0.0f;

    // A: 1024 float4-chunks / stage, 4 per thread.  idx = tid + i*256,
    // row = idx>>3 (8 chunks per 32-float row), c4 = (idx&7)*4 floats.
    auto ldgA = [&](int kt, float4* pa) {
        const int k0 = kt * BK;
        #pragma unroll
        for (int i = 0; i < 4; i++) {
            int idx = tid + i * 256, r = idx >> 3, c4 = (idx & 7) * 4;
            pa[i] = *(const float4*)&X[(size_t)(m0b + r) * Dd + k0 + c4];
        }
    };
    auto stsA = [&](int kt, const float4* pa) {
        const int slot = kt & (NSTG - 1);
        __half* dst = &As[slot * A_STGH];
        #pragma unroll
        for (int i = 0; i < 4; i++) {
            int idx = tid + i * 256, r = idx >> 3, c4 = (idx & 7) * 4;
            __half2 h0 = __floats2half2_rn(pa[i].x, pa[i].y);
            __half2 h1 = __floats2half2_rn(pa[i].z, pa[i].w);
            uint2 o;
            o.x = *reinterpret_cast<unsigned*>(&h0);
            o.y = *reinterpret_cast<unsigned*>(&h1);
            *(uint2*)&dst[r * PITH + c4] = o;
        }
    };
    // B: 1024 16B-chunks / stage (256 rows x 4 chunks of 8 halves), 4/thread.
    auto cpB = [&](int kt) {
        const int slot = kt & (NSTG - 1);
        const int k0   = kt * BK;
        const uint32_t bbase = sB + slot * B_STGH * 2;
        #pragma unroll
        for (int i = 0; i < 4; i++) {
            int idx = tid + i * 256, r = idx >> 2, c = idx & 3;
            cp16s(bbase + (r * PITH + c * 8) * 2,
                  &g_Wh[(size_t)(n0b + r) * Dd + k0 + c * 8]);
        }
        cp_commit();
    };

    float4 pa0[4], pa1[4];
    ldgA(0, pa0);
    ldgA(1, pa1);
    cpB(0); cpB(1); cpB(2);

    for (int kt = 0; kt < NKT; kt++) {
        float4* pcur = (kt & 1) ? pa1 : pa0;
        stsA(kt, pcur);
        if (kt + 2 < NKT) ldgA(kt + 2, pcur);
        if (kt + 3 < NKT) cpB(kt + 3);
        else cp_commit();                 // keep group accounting exact at tail

        cp_wait<3>();                     // B stage kt landed
        __syncthreads();                  // + A STS visible

        const int slot = kt & (NSTG - 1);
        const __half* Asl = &As[slot * A_STGH];
        const __half* Bsl = &Bs[slot * B_STGH];

        #pragma unroll
        for (int kf = 0; kf < BK; kf += 16) {
            unsigned af[4][4], bf[8][2];
            #pragma unroll
            for (int mi = 0; mi < 4; mi++) {
                int base = (wm0 + mi * 16 + g) * PITH + kf + 2 * q;
                af[mi][0] = *(const unsigned*)&Asl[base];
                af[mi][1] = *(const unsigned*)&Asl[base + 8 * PITH];
                af[mi][2] = *(const unsigned*)&Asl[base + 8];
                af[mi][3] = *(const unsigned*)&Asl[base + 8 * PITH + 8];
            }
            #pragma unroll
            for (int ni = 0; ni < 8; ni++) {
                int base = (wn0 + ni * 8 + g) * PITH + kf + 2 * q;
                bf[ni][0] = *(const unsigned*)&Bsl[base];
                bf[ni][1] = *(const unsigned*)&Bsl[base + 8];
            }
            #pragma unroll
            for (int mi = 0; mi < 4; mi++)
                #pragma unroll
                for (int ni = 0; ni < 8; ni++)
                    mma_f16(acc[mi][ni], af[mi], bf[ni]);
        }
        __syncthreads();
    }

    // Epilogue: bias + sigmoid -> g_lamh (fp16, half2 stores)
    #pragma unroll
    for (int ni = 0; ni < 8; ni++) {
        const int c0 = n0b + wn0 + ni * 8 + 2 * q;
        const float b0 = bias[c0];
        const float b1 = bias[c0 + 1];
        #pragma unroll
        for (int mi = 0; mi < 4; mi++) {
            const int r0 = m0b + wm0 + mi * 16 + g;
            float z0 = acc[mi][ni][0] + b0, z1 = acc[mi][ni][1] + b1;
            float z2 = acc[mi][ni][2] + b0, z3 = acc[mi][ni][3] + b1;
            __half2 h0 = __floats2half2_rn(1.0f / (1.0f + __expf(-z0)),
                                           1.0f / (1.0f + __expf(-z1)));
            __half2 h1 = __floats2half2_rn(1.0f / (1.0f + __expf(-z2)),
                                           1.0f / (1.0f + __expf(-z3)));
            *(__half2*)&g_lamh[(size_t)r0 * Dd + c0]       = h0;
            *(__half2*)&g_lamh[(size_t)(r0 + 8) * Dd + c0] = h1;
        }
    }
}

// ---------------------------------------------------------------------------
// Scan phase 1: per (channel, chunk): A = prod(lam), S = local scan (s0=0)
// ---------------------------------------------------------------------------
__global__ __launch_bounds__(256) void scan_phase1(const float* __restrict__ X)
{
    const int d = blockIdx.x * 256 + threadIdx.x;
    const int b = blockIdx.y;
    const int c = blockIdx.z;
    size_t base = ((size_t)(b * Kk + c * LCH)) * Dd + d;

    float s = 0.0f, A = 1.0f;
    #pragma unroll 8
    for (int k = 0; k < LCH; k++) {
        size_t idx = base + (size_t)k * Dd;
        float lam = __half2float(g_lamh[idx]);
        float xv  = X[idx];
        s = fmaf(lam, s - xv, xv);   // s = lam*s + (1-lam)*x
        A *= lam;
    }
    const int ch = b * Dd + d;
    g_A[c * CHN + ch] = A;
    g_S[c * CHN + ch] = s;
}

// ---------------------------------------------------------------------------
// Scan phase 2: sequential combine of 32 chunk summaries per channel (tiny).
// ---------------------------------------------------------------------------
__global__ __launch_bounds__(256) void scan_phase2()
{
    const int ch = blockIdx.x * 256 + threadIdx.x;
    float s = 0.0f;
    #pragma unroll
    for (int c = 0; c < NCH; c++) {
        g_P[c * CHN + ch] = s;
        s = fmaf(g_A[c * CHN + ch], s, g_S[c * CHN + ch]);
    }
}

// ---------------------------------------------------------------------------
// Scan phase 3: re-scan each chunk starting from its prefix; write output.
// ---------------------------------------------------------------------------
__global__ __launch_bounds__(256) void scan_phase3(const float* __restrict__ X,
                                                   float* __restrict__ out)
{
    const int d = blockIdx.x * 256 + threadIdx.x;
    const int b = blockIdx.y;
    const int c = blockIdx.z;
    const int ch = b * Dd + d;
    size_t base = ((size_t)(b * Kk + c * LCH)) * Dd + d;

    float s = g_P[c * CHN + ch];
    #pragma unroll 8
    for (int k = 0; k < LCH; k++) {
        size_t idx = base + (size_t)k * Dd;
        float lam = __half2float(g_lamh[idx]);
        float xv  = X[idx];
        s = fmaf(lam, s - xv, xv);
        out[idx] = s;
    }
}

// ---------------------------------------------------------------------------
extern "C" void kernel_launch(void* const* d_in, const int* in_sizes, int n_in,
                              void* d_out, int out_size)
{
    const float* X    = (const float*)d_in[0];  // [B,K,D]
    const float* W    = (const float*)d_in[1];  // [D,D]
    const float* bias = (const float*)d_in[2];  // [D]
    float* out        = (float*)d_out;          // [B,K,D]

    // fp16 conversion for W only (2 MiB)
    __half* Wh; cudaGetSymbolAddress((void**)&Wh, g_Wh);
    f2h_kernel<<<256, 256>>>((const float4*)W, (uint2*)Wh, (Dd * Dd) / 4);

    const int smem_bytes = SMEM_HALVES * (int)sizeof(__half);   // 120 KB
    cudaFuncSetAttribute(gemm_sigmoid_f16,
                         cudaFuncAttributeMaxDynamicSharedMemorySize, smem_bytes);

    dim3 gemm_grid(Dd / BN, Mm / BM);           // (4, 256)
    gemm_sigmoid_f16<<<gemm_grid, 256, smem_bytes>>>(X, bias);

    dim3 scan_grid(Dd / 256, Bb, NCH);          // (4, 4, 32)
    scan_phase1<<<scan_grid, 256>>>(X);
    scan_phase2<<<CHN / 256, 256>>>();
    scan_phase3<<<scan_grid, 256>>>(X, out);
}

// round 7
// speedup vs baseline: 1.2173x; 1.2173x over previous
#include <cuda_runtime.h>
#include <cuda_fp16.h>
#include <cstdint>
#include <math.h>

// Problem shape (fixed)
#define Bb  4
#define Kk  8192
#define Dd  1024
#define Mm  (Bb * Kk)          // 32768 GEMM rows
#define NCH 32                 // scan chunks along K
#define LCH (Kk / NCH)         // 256 steps per chunk
#define CHN (Bb * Dd)          // 4096 independent channels

// Scratch (allocation-free rule: __device__ globals)
__device__ __half g_lamh[(size_t)Mm * Dd];    // 64 MiB fp16 lam
__device__ __half g_Xh[(size_t)Mm * Dd];      // 64 MiB fp16 X
__device__ __half g_Wh[(size_t)Dd * Dd];      // 2 MiB fp16 W
__device__ float  g_A[NCH * CHN];
__device__ float  g_S[NCH * CHN];
__device__ float  g_P[NCH * CHN];

// ---------------------------------------------------------------------------
// f32 -> f16 conversion (X and W), vectorized
// ---------------------------------------------------------------------------
__global__ __launch_bounds__(256) void f2h_kernel(const float4* __restrict__ src,
                                                  uint2* __restrict__ dst, int n4)
{
    int i = blockIdx.x * blockDim.x + threadIdx.x;
    const int stride = gridDim.x * blockDim.x;
    for (; i < n4; i += stride) {
        float4 v = src[i];
        __half2 h0 = __floats2half2_rn(v.x, v.y);
        __half2 h1 = __floats2half2_rn(v.z, v.w);
        uint2 o;
        o.x = *reinterpret_cast<unsigned*>(&h0);
        o.y = *reinterpret_cast<unsigned*>(&h1);
        dst[i] = o;
    }
}

// ---------------------------------------------------------------------------
// FP16 tensor-core GEMM + sigmoid epilogue:  g_lamh = sigmoid(X @ W^T + b)
// 256 threads, BM=128 x BN=256, BK=32, 2x4 warps of 64x64, m16n8k16 HMMA,
// 4-stage cp.async pipeline, pitch-40-halves smem (banks (20g+q)%32 distinct).
// ---------------------------------------------------------------------------
#define BM 128
#define BN 256
#define BK 32
#define PITH 40                          // smem row pitch in halves (80 B)
#define NSTG 4
#define A_STGH (BM * PITH)               // 5120 halves / stage
#define B_STGH (BN * PITH)               // 10240 halves / stage
#define SMEM_HALVES (NSTG * (A_STGH + B_STGH))   // 61440 halves = 122880 B
#define NKT (Dd / BK)                    // 32 k-stages

__device__ __forceinline__ void cp16s(uint32_t smem_dst, const void* gmem_src) {
    asm volatile("cp.async.cg.shared.global [%0], [%1], 16;\n"
                 :: "r"(smem_dst), "l"(gmem_src));
}
__device__ __forceinline__ void cp_commit() {
    asm volatile("cp.async.commit_group;\n");
}
template <int N>
__device__ __forceinline__ void cp_wait() {
    asm volatile("cp.async.wait_group %0;\n" :: "n"(N));
}
__device__ __forceinline__ void mma_f16(float* d, const unsigned* a, const unsigned* b) {
    asm volatile(
        "mma.sync.aligned.m16n8k16.row.col.f32.f16.f16.f32 "
        "{%0,%1,%2,%3}, {%4,%5,%6,%7}, {%8,%9}, {%0,%1,%2,%3};\n"
        : "+f"(d[0]), "+f"(d[1]), "+f"(d[2]), "+f"(d[3])
        : "r"(a[0]), "r"(a[1]), "r"(a[2]), "r"(a[3]), "r"(b[0]), "r"(b[1]));
}

extern __shared__ __half smemh[];

__global__ __launch_bounds__(256, 1) void gemm_sigmoid_f16(
    const float* __restrict__ bias)
{
    __half* As = smemh;                  // [NSTG][BM][PITH]
    __half* Bs = smemh + NSTG * A_STGH;  // [NSTG][BN][PITH]

    const int tid  = threadIdx.x;
    const int lane = tid & 31;
    const int wid  = tid >> 5;           // 8 warps: 2 (m) x 4 (n)
    const int wm0  = (wid & 1) * 64;
    const int wn0  = (wid >> 1) * 64;
    const int g    = lane >> 2;          // 0..7
    const int q    = lane & 3;           // 0..3
    const int m0b  = blockIdx.y * BM;
    const int n0b  = blockIdx.x * BN;

    const uint32_t sA = (uint32_t)__cvta_generic_to_shared(As);
    const uint32_t sB = (uint32_t)__cvta_generic_to_shared(Bs);

    float acc[4][8][4];
    #pragma unroll
    for (int mi = 0; mi < 4; mi++)
        #pragma unroll
        for (int ni = 0; ni < 8; ni++)
            #pragma unroll
            for (int r = 0; r < 4; r++)
                acc[mi][ni][r] = 0.0f;

    // --- async stage loader: A 512 + B 1024 = 1536 16B-chunks, 6/thread ---
    auto load_stage = [&](int kt) {
        const int slot = kt & (NSTG - 1);
        const int k0   = kt * BK;
        const uint32_t abase = sA + slot * A_STGH * 2;
        const uint32_t bbase = sB + slot * B_STGH * 2;
        #pragma unroll
        for (int i = 0; i < 6; i++) {
            int idx = tid + i * 256;
            if (idx < 512) {                   // A: 128 rows x 4 chunks (8 halves)
                int r = idx >> 2, c = idx & 3;
                cp16s(abase + (r * PITH + c * 8) * 2,
                      &g_Xh[(size_t)(m0b + r) * Dd + k0 + c * 8]);
            } else {                           // B: 256 rows x 4 chunks
                int j = idx - 512;
                int r = j >> 2, c = j & 3;
                cp16s(bbase + (r * PITH + c * 8) * 2,
                      &g_Wh[(size_t)(n0b + r) * Dd + k0 + c * 8]);
            }
        }
        cp_commit();
    };

    load_stage(0);
    load_stage(1);
    load_stage(2);

    for (int kt = 0; kt < NKT; kt++) {
        if (kt + 3 < NKT) load_stage(kt + 3);
        else cp_commit();                  // keep group accounting exact at tail
        cp_wait<3>();                      // stage kt landed
        __syncthreads();

        const int slot = kt & (NSTG - 1);
        const __half* Asl = &As[slot * A_STGH];
        const __half* Bsl = &Bs[slot * B_STGH];

        #pragma unroll
        for (int kf = 0; kf < BK; kf += 16) {
            unsigned af[4][4], bf[8][2];
            #pragma unroll
            for (int mi = 0; mi < 4; mi++) {
                int base = (wm0 + mi * 16 + g) * PITH + kf + 2 * q;
                af[mi][0] = *(const unsigned*)&Asl[base];
                af[mi][1] = *(const unsigned*)&Asl[base + 8 * PITH];
                af[mi][2] = *(const unsigned*)&Asl[base + 8];
                af[mi][3] = *(const unsigned*)&Asl[base + 8 * PITH + 8];
            }
            #pragma unroll
            for (int ni = 0; ni < 8; ni++) {
                int base = (wn0 + ni * 8 + g) * PITH + kf + 2 * q;
                bf[ni][0] = *(const unsigned*)&Bsl[base];
                bf[ni][1] = *(const unsigned*)&Bsl[base + 8];
            }
            #pragma unroll
            for (int mi = 0; mi < 4; mi++)
                #pragma unroll
                for (int ni = 0; ni < 8; ni++)
                    mma_f16(acc[mi][ni], af[mi], bf[ni]);
        }
        __syncthreads();
    }

    // Epilogue: bias + sigmoid -> g_lamh (fp16, half2 stores; c0 always even)
    #pragma unroll
    for (int ni = 0; ni < 8; ni++) {
        const int c0 = n0b + wn0 + ni * 8 + 2 * q;
        const float b0 = bias[c0];
        const float b1 = bias[c0 + 1];
        #pragma unroll
        for (int mi = 0; mi < 4; mi++) {
            const int r0 = m0b + wm0 + mi * 16 + g;
            float z0 = acc[mi][ni][0] + b0, z1 = acc[mi][ni][1] + b1;
            float z2 = acc[mi][ni][2] + b0, z3 = acc[mi][ni][3] + b1;
            __half2 h0 = __floats2half2_rn(1.0f / (1.0f + __expf(-z0)),
                                           1.0f / (1.0f + __expf(-z1)));
            __half2 h1 = __floats2half2_rn(1.0f / (1.0f + __expf(-z2)),
                                           1.0f / (1.0f + __expf(-z3)));
            *(__half2*)&g_lamh[(size_t)r0 * Dd + c0]       = h0;
            *(__half2*)&g_lamh[(size_t)(r0 + 8) * Dd + c0] = h1;
        }
    }
}

// ---------------------------------------------------------------------------
// Scan phase 1: 2 channels/thread (half2), per (chunk): A = prod, S = local scan
// ---------------------------------------------------------------------------
__global__ __launch_bounds__(256) void scan_phase1()
{
    const int d2 = blockIdx.x * 256 + threadIdx.x;   // 0..511
    const int d  = d2 * 2;
    const int b  = blockIdx.y;
    const int c  = blockIdx.z;
    size_t base = ((size_t)(b * Kk + c * LCH)) * Dd + d;

    float s0 = 0.0f, s1 = 0.0f, A0 = 1.0f, A1 = 1.0f;
    #pragma unroll 8
    for (int k = 0; k < LCH; k++) {
        size_t idx = base + (size_t)k * Dd;
        float2 lam = __half22float2(*(const __half2*)&g_lamh[idx]);
        float2 xv  = __half22float2(*(const __half2*)&g_Xh[idx]);
        s0 = fmaf(lam.x, s0 - xv.x, xv.x);
        s1 = fmaf(lam.y, s1 - xv.y, xv.y);
        A0 *= lam.x;
        A1 *= lam.y;
    }
    const int ch = b * Dd + d;
    *(float2*)&g_A[c * CHN + ch] = make_float2(A0, A1);
    *(float2*)&g_S[c * CHN + ch] = make_float2(s0, s1);
}

// ---------------------------------------------------------------------------
// Scan phase 2: warp-shfl scan over 32 chunks; one warp per channel.
// Compose (A,S) o (Ap,Sp) = (A*Ap, A*Sp + S); g_P[c] = Q_{c-1}, Q_{-1}=0.
// ---------------------------------------------------------------------------
__global__ __launch_bounds__(256) void scan_phase2()
{
    const int lane = threadIdx.x & 31;               // chunk index
    const int ch   = blockIdx.x * 8 + (threadIdx.x >> 5);
    float A = g_A[lane * CHN + ch];
    float S = g_S[lane * CHN + ch];
    #pragma unroll
    for (int off = 1; off < 32; off <<= 1) {
        float Ap = __shfl_up_sync(0xffffffffu, A, off);
        float Sp = __shfl_up_sync(0xffffffffu, S, off);
        if (lane >= off) { S = fmaf(A, Sp, S); A *= Ap; }
    }
    float P = __shfl_up_sync(0xffffffffu, S, 1);
    if (lane == 0) P = 0.0f;
    g_P[lane * CHN + ch] = P;
}

// ---------------------------------------------------------------------------
// Scan phase 3: re-scan each chunk from its prefix; write fp32 output.
// ---------------------------------------------------------------------------
__global__ __launch_bounds__(256) void scan_phase3(float* __restrict__ out)
{
    const int d2 = blockIdx.x * 256 + threadIdx.x;
    const int d  = d2 * 2;
    const int b  = blockIdx.y;
    const int c  = blockIdx.z;
    const int ch = b * Dd + d;
    size_t base = ((size_t)(b * Kk + c * LCH)) * Dd + d;

    float2 p = *(const float2*)&g_P[c * CHN + ch];
    float s0 = p.x, s1 = p.y;
    #pragma unroll 8
    for (int k = 0; k < LCH; k++) {
        size_t idx = base + (size_t)k * Dd;
        float2 lam = __half22float2(*(const __half2*)&g_lamh[idx]);
        float2 xv  = __half22float2(*(const __half2*)&g_Xh[idx]);
        s0 = fmaf(lam.x, s0 - xv.x, xv.x);
        s1 = fmaf(lam.y, s1 - xv.y, xv.y);
        *(float2*)&out[idx] = make_float2(s0, s1);
    }
}

// ---------------------------------------------------------------------------
extern "C" void kernel_launch(void* const* d_in, const int* in_sizes, int n_in,
                              void* d_out, int out_size)
{
    const float* X    = (const float*)d_in[0];  // [B,K,D]
    const float* W    = (const float*)d_in[1];  // [D,D]
    const float* bias = (const float*)d_in[2];  // [D]
    float* out        = (float*)d_out;          // [B,K,D]

    __half* Xh; cudaGetSymbolAddress((void**)&Xh, g_Xh);
    __half* Wh; cudaGetSymbolAddress((void**)&Wh, g_Wh);
    f2h_kernel<<<1024, 256>>>((const float4*)X, (uint2*)Xh, (Mm * Dd) / 4);
    f2h_kernel<<<256, 256>>>((const float4*)W, (uint2*)Wh, (Dd * Dd) / 4);

    const int smem_bytes = SMEM_HALVES * (int)sizeof(__half);   // 120 KB
    cudaFuncSetAttribute(gemm_sigmoid_f16,
                         cudaFuncAttributeMaxDynamicSharedMemorySize, smem_bytes);

    dim3 gemm_grid(Dd / BN, Mm / BM);           // (4, 256)
    gemm_sigmoid_f16<<<gemm_grid, 256, smem_bytes>>>(bias);

    dim3 scan_grid(Dd / 512, Bb, NCH);          // (2, 4, 32)
    scan_phase1<<<scan_grid, 256>>>();
    scan_phase2<<<CHN / 8, 256>>>();
    scan_phase3<<<scan_grid, 256>>>(out);
}

// round 8
// speedup vs baseline: 1.2878x; 1.0579x over previous
#include <cuda_runtime.h>
#include <cuda_fp16.h>
#include <cstdint>
#include <math.h>

// Problem shape (fixed)
#define Bb  4
#define Kk  8192
#define Dd  1024
#define Mm  (Bb * Kk)          // 32768 GEMM rows
#define NCH 128                // scan chunks along K
#define LCH (Kk / NCH)         // 64 steps per chunk
#define CHN (Bb * Dd)          // 4096 independent channels

// Scratch (allocation-free rule: __device__ globals)
__device__ __half g_lamh[(size_t)Mm * Dd];    // 64 MiB fp16 lam
__device__ __half g_Xh[(size_t)Mm * Dd];      // 64 MiB fp16 X
__device__ __half g_Wh[(size_t)Dd * Dd];      // 2 MiB fp16 W
__device__ float  g_A[NCH * CHN];
__device__ float  g_S[NCH * CHN];
__device__ float  g_P[NCH * CHN];

// ---------------------------------------------------------------------------
// f32 -> f16 conversion (X and W), vectorized
// ---------------------------------------------------------------------------
__global__ __launch_bounds__(256) void f2h_kernel(const float4* __restrict__ src,
                                                  uint2* __restrict__ dst, int n4)
{
    int i = blockIdx.x * blockDim.x + threadIdx.x;
    const int stride = gridDim.x * blockDim.x;
    for (; i < n4; i += stride) {
        float4 v = src[i];
        __half2 h0 = __floats2half2_rn(v.x, v.y);
        __half2 h1 = __floats2half2_rn(v.z, v.w);
        uint2 o;
        o.x = *reinterpret_cast<unsigned*>(&h0);
        o.y = *reinterpret_cast<unsigned*>(&h1);
        dst[i] = o;
    }
}

// ---------------------------------------------------------------------------
// FP16 tensor-core GEMM + sigmoid epilogue:  g_lamh = sigmoid(X @ W^T + b)
// 256 threads, BM=128 x BN=256, BK=32, 2x4 warps of 64x64, m16n8k16 HMMA,
// 4-stage cp.async pipeline, pitch-40-halves smem (banks (20g+q)%32 distinct).
// ---------------------------------------------------------------------------
#define BM 128
#define BN 256
#define BK 32
#define PITH 40                          // smem row pitch in halves (80 B)
#define NSTG 4
#define A_STGH (BM * PITH)               // 5120 halves / stage
#define B_STGH (BN * PITH)               // 10240 halves / stage
#define SMEM_HALVES (NSTG * (A_STGH + B_STGH))   // 61440 halves = 122880 B
#define NKT (Dd / BK)                    // 32 k-stages

__device__ __forceinline__ void cp16s(uint32_t smem_dst, const void* gmem_src) {
    asm volatile("cp.async.cg.shared.global [%0], [%1], 16;\n"
                 :: "r"(smem_dst), "l"(gmem_src));
}
__device__ __forceinline__ void cp_commit() {
    asm volatile("cp.async.commit_group;\n");
}
template <int N>
__device__ __forceinline__ void cp_wait() {
    asm volatile("cp.async.wait_group %0;\n" :: "n"(N));
}
__device__ __forceinline__ void mma_f16(float* d, const unsigned* a, const unsigned* b) {
    asm volatile(
        "mma.sync.aligned.m16n8k16.row.col.f32.f16.f16.f32 "
        "{%0,%1,%2,%3}, {%4,%5,%6,%7}, {%8,%9}, {%0,%1,%2,%3};\n"
        : "+f"(d[0]), "+f"(d[1]), "+f"(d[2]), "+f"(d[3])
        : "r"(a[0]), "r"(a[1]), "r"(a[2]), "r"(a[3]), "r"(b[0]), "r"(b[1]));
}

extern __shared__ __half smemh[];

__global__ __launch_bounds__(256, 1) void gemm_sigmoid_f16(
    const float* __restrict__ bias)
{
    __half* As = smemh;                  // [NSTG][BM][PITH]
    __half* Bs = smemh + NSTG * A_STGH;  // [NSTG][BN][PITH]

    const int tid  = threadIdx.x;
    const int lane = tid & 31;
    const int wid  = tid >> 5;           // 8 warps: 2 (m) x 4 (n)
    const int wm0  = (wid & 1) * 64;
    const int wn0  = (wid >> 1) * 64;
    const int g    = lane >> 2;          // 0..7
    const int q    = lane & 3;           // 0..3
    const int m0b  = blockIdx.y * BM;
    const int n0b  = blockIdx.x * BN;

    const uint32_t sA = (uint32_t)__cvta_generic_to_shared(As);
    const uint32_t sB = (uint32_t)__cvta_generic_to_shared(Bs);

    float acc[4][8][4];
    #pragma unroll
    for (int mi = 0; mi < 4; mi++)
        #pragma unroll
        for (int ni = 0; ni < 8; ni++)
            #pragma unroll
            for (int r = 0; r < 4; r++)
                acc[mi][ni][r] = 0.0f;

    // --- async stage loader: A 512 + B 1024 = 1536 16B-chunks, 6/thread ---
    auto load_stage = [&](int kt) {
        const int slot = kt & (NSTG - 1);
        const int k0   = kt * BK;
        const uint32_t abase = sA + slot * A_STGH * 2;
        const uint32_t bbase = sB + slot * B_STGH * 2;
        #pragma unroll
        for (int i = 0; i < 6; i++) {
            int idx = tid + i * 256;
            if (idx < 512) {                   // A: 128 rows x 4 chunks (8 halves)
                int r = idx >> 2, c = idx & 3;
                cp16s(abase + (r * PITH + c * 8) * 2,
                      &g_Xh[(size_t)(m0b + r) * Dd + k0 + c * 8]);
            } else {                           // B: 256 rows x 4 chunks
                int j = idx - 512;
                int r = j >> 2, c = j & 3;
                cp16s(bbase + (r * PITH + c * 8) * 2,
                      &g_Wh[(size_t)(n0b + r) * Dd + k0 + c * 8]);
            }
        }
        cp_commit();
    };

    load_stage(0);
    load_stage(1);
    load_stage(2);

    for (int kt = 0; kt < NKT; kt++) {
        if (kt + 3 < NKT) load_stage(kt + 3);
        else cp_commit();                  // keep group accounting exact at tail
        cp_wait<3>();                      // stage kt landed
        __syncthreads();

        const int slot = kt & (NSTG - 1);
        const __half* Asl = &As[slot * A_STGH];
        const __half* Bsl = &Bs[slot * B_STGH];

        #pragma unroll
        for (int kf = 0; kf < BK; kf += 16) {
            unsigned af[4][4], bf[8][2];
            #pragma unroll
            for (int mi = 0; mi < 4; mi++) {
                int base = (wm0 + mi * 16 + g) * PITH + kf + 2 * q;
                af[mi][0] = *(const unsigned*)&Asl[base];
                af[mi][1] = *(const unsigned*)&Asl[base + 8 * PITH];
                af[mi][2] = *(const unsigned*)&Asl[base + 8];
                af[mi][3] = *(const unsigned*)&Asl[base + 8 * PITH + 8];
            }
            #pragma unroll
            for (int ni = 0; ni < 8; ni++) {
                int base = (wn0 + ni * 8 + g) * PITH + kf + 2 * q;
                bf[ni][0] = *(const unsigned*)&Bsl[base];
                bf[ni][1] = *(const unsigned*)&Bsl[base + 8];
            }
            #pragma unroll
            for (int mi = 0; mi < 4; mi++)
                #pragma unroll
                for (int ni = 0; ni < 8; ni++)
                    mma_f16(acc[mi][ni], af[mi], bf[ni]);
        }
        __syncthreads();
    }

    // Epilogue: bias + sigmoid -> g_lamh (fp16, half2 stores; c0 always even)
    #pragma unroll
    for (int ni = 0; ni < 8; ni++) {
        const int c0 = n0b + wn0 + ni * 8 + 2 * q;
        const float b0 = bias[c0];
        const float b1 = bias[c0 + 1];
        #pragma unroll
        for (int mi = 0; mi < 4; mi++) {
            const int r0 = m0b + wm0 + mi * 16 + g;
            float z0 = acc[mi][ni][0] + b0, z1 = acc[mi][ni][1] + b1;
            float z2 = acc[mi][ni][2] + b0, z3 = acc[mi][ni][3] + b1;
            __half2 h0 = __floats2half2_rn(1.0f / (1.0f + __expf(-z0)),
                                           1.0f / (1.0f + __expf(-z1)));
            __half2 h1 = __floats2half2_rn(1.0f / (1.0f + __expf(-z2)),
                                           1.0f / (1.0f + __expf(-z3)));
            *(__half2*)&g_lamh[(size_t)r0 * Dd + c0]       = h0;
            *(__half2*)&g_lamh[(size_t)(r0 + 8) * Dd + c0] = h1;
        }
    }
}

// ---------------------------------------------------------------------------
// Scan phase 1: 2 channels/thread (half2), per (chunk): A = prod, S = local scan
// grid (2, 4, 128) = 1024 blocks -> ~full wave of 148 SMs.
// ---------------------------------------------------------------------------
__global__ __launch_bounds__(256) void scan_phase1()
{
    const int d2 = blockIdx.x * 256 + threadIdx.x;   // 0..511
    const int d  = d2 * 2;
    const int b  = blockIdx.y;
    const int c  = blockIdx.z;
    size_t base = ((size_t)(b * Kk + c * LCH)) * Dd + d;

    float s0 = 0.0f, s1 = 0.0f, A0 = 1.0f, A1 = 1.0f;
    #pragma unroll 8
    for (int k = 0; k < LCH; k++) {
        size_t idx = base + (size_t)k * Dd;
        float2 lam = __half22float2(*(const __half2*)&g_lamh[idx]);
        float2 xv  = __half22float2(*(const __half2*)&g_Xh[idx]);
        s0 = fmaf(lam.x, s0 - xv.x, xv.x);
        s1 = fmaf(lam.y, s1 - xv.y, xv.y);
        A0 *= lam.x;
        A1 *= lam.y;
    }
    const int ch = b * Dd + d;
    *(float2*)&g_A[c * CHN + ch] = make_float2(A0, A1);
    *(float2*)&g_S[c * CHN + ch] = make_float2(s0, s1);
}

// ---------------------------------------------------------------------------
// Scan phase 2: 128 chunks per channel; one warp per channel, 4 chunks/lane.
// Compose rule (apply P then Q): (A,S) = (Aq*Ap, Aq*Sp + Sq). s0 = 0 so the
// incoming state of a chunk is just the S of the composed prefix.
// ---------------------------------------------------------------------------
__global__ __launch_bounds__(256) void scan_phase2()
{
    const int lane = threadIdx.x & 31;
    const int ch   = blockIdx.x * 8 + (threadIdx.x >> 5);

    float A[4], S[4];
    #pragma unroll
    for (int j = 0; j < 4; j++) {
        A[j] = g_A[(4 * lane + j) * CHN + ch];
        S[j] = g_S[(4 * lane + j) * CHN + ch];
    }
    // serial combine of this lane's 4 chunks (in k-order)
    float Ac = A[0], Sc = S[0];
    #pragma unroll
    for (int j = 1; j < 4; j++) { Sc = fmaf(A[j], Sc, S[j]); Ac *= A[j]; }

    // warp inclusive scan over lane-composites
    #pragma unroll
    for (int off = 1; off < 32; off <<= 1) {
        float Ap = __shfl_up_sync(0xffffffffu, Ac, off);
        float Sp = __shfl_up_sync(0xffffffffu, Sc, off);
        if (lane >= off) { Sc = fmaf(Ac, Sp, Sc); Ac *= Ap; }
    }
    // exclusive prefix state entering this lane's first chunk
    float Pbase = __shfl_up_sync(0xffffffffu, Sc, 1);
    if (lane == 0) Pbase = 0.0f;

    // per-chunk prefixes within the lane
    float s = Pbase;
    #pragma unroll
    for (int j = 0; j < 4; j++) {
        g_P[(4 * lane + j) * CHN + ch] = s;
        s = fmaf(A[j], s, S[j]);
    }
}

// ---------------------------------------------------------------------------
// Scan phase 3: re-scan each chunk from its prefix; write fp32 output.
// ---------------------------------------------------------------------------
__global__ __launch_bounds__(256) void scan_phase3(float* __restrict__ out)
{
    const int d2 = blockIdx.x * 256 + threadIdx.x;
    const int d  = d2 * 2;
    const int b  = blockIdx.y;
    const int c  = blockIdx.z;
    const int ch = b * Dd + d;
    size_t base = ((size_t)(b * Kk + c * LCH)) * Dd + d;

    float2 p = *(const float2*)&g_P[c * CHN + ch];
    float s0 = p.x, s1 = p.y;
    #pragma unroll 8
    for (int k = 0; k < LCH; k++) {
        size_t idx = base + (size_t)k * Dd;
        float2 lam = __half22float2(*(const __half2*)&g_lamh[idx]);
        float2 xv  = __half22float2(*(const __half2*)&g_Xh[idx]);
        s0 = fmaf(lam.x, s0 - xv.x, xv.x);
        s1 = fmaf(lam.y, s1 - xv.y, xv.y);
        *(float2*)&out[idx] = make_float2(s0, s1);
    }
}

// ---------------------------------------------------------------------------
extern "C" void kernel_launch(void* const* d_in, const int* in_sizes, int n_in,
                              void* d_out, int out_size)
{
    const float* X    = (const float*)d_in[0];  // [B,K,D]
    const float* W    = (const float*)d_in[1];  // [D,D]
    const float* bias = (const float*)d_in[2];  // [D]
    float* out        = (float*)d_out;          // [B,K,D]

    __half* Xh; cudaGetSymbolAddress((void**)&Xh, g_Xh);
    __half* Wh; cudaGetSymbolAddress((void**)&Wh, g_Wh);
    f2h_kernel<<<1024, 256>>>((const float4*)X, (uint2*)Xh, (Mm * Dd) / 4);
    f2h_kernel<<<256, 256>>>((const float4*)W, (uint2*)Wh, (Dd * Dd) / 4);

    const int smem_bytes = SMEM_HALVES * (int)sizeof(__half);   // 120 KB
    cudaFuncSetAttribute(gemm_sigmoid_f16,
                         cudaFuncAttributeMaxDynamicSharedMemorySize, smem_bytes);

    dim3 gemm_grid(Dd / BN, Mm / BM);           // (4, 256)
    gemm_sigmoid_f16<<<gemm_grid, 256, smem_bytes>>>(bias);

    dim3 scan_grid(Dd / 512, Bb, NCH);          // (2, 4, 128)
    scan_phase1<<<scan_grid, 256>>>();
    scan_phase2<<<CHN / 8, 256>>>();
    scan_phase3<<<scan_grid, 256>>>(out);
}